// round 1
// baseline (speedup 1.0000x reference)
#include <cuda_runtime.h>
#include <math.h>

#define NROWS 4096
#define NW 128          // adjacency bitmask words per row (4096/32)
#define HID 64
#define ALPHA 0.2f
#define BR 64           // attention rows per block
#define BM 32           // attention m-chunk

// ---------------- device scratch (globals: no allocation allowed) ----------------
__device__ unsigned int g_adjbits[NROWS * NW];       // 2 MB packed adjacency
__device__ float g_h[4 * NROWS * HID];               // per-layer head features (4 MB)
__device__ float g_el[4 * NROWS];
__device__ float g_er[4 * NROWS];
__device__ float g_emax[4];
__device__ float g_buf[NROWS * 256];                 // inter-layer activations (4 MB)

// ---------------- helpers ----------------
__device__ __forceinline__ unsigned long long pack2(float x) {
    unsigned long long r;
    asm("mov.b64 %0, {%1, %1};" : "=l"(r) : "f"(x));
    return r;
}
__device__ __forceinline__ void fma2(unsigned long long& d, unsigned long long a, unsigned long long b) {
    asm("fma.rn.f32x2 %0, %1, %2, %0;" : "+l"(d) : "l"(a), "l"(b));
}
__device__ __forceinline__ float2 unpack2(unsigned long long v) {
    float2 f;
    asm("mov.b64 {%0, %1}, %2;" : "=f"(f.x), "=f"(f.y) : "l"(v));
    return f;
}

// ---------------- 1. pack adjacency into bitmask ----------------
__global__ void pack_adj_kernel(const int* __restrict__ adj) {
    int n = blockIdx.x;
    int warp = threadIdx.x >> 5, lane = threadIdx.x & 31;
    const int* row = adj + (size_t)n * NROWS;
    #pragma unroll 4
    for (int w = warp * 32; w < warp * 32 + 32; w++) {
        int v = row[w * 32 + lane];
        unsigned int bits = __ballot_sync(0xffffffffu, v > 0);
        if (lane == 0) g_adjbits[n * NW + w] = bits;
    }
}

// ---------------- 2. feature GEMM: g_h[head][n][o] = X @ W[head] ----------------
__global__ __launch_bounds__(256) void gemm_kernel(const float* __restrict__ Xext,
                                                   const float* __restrict__ W,
                                                   int D, int useBuf) {
    const float* __restrict__ X = useBuf ? (const float*)g_buf : Xext;
    const int head = blockIdx.y;
    const int r0 = blockIdx.x * 64;
    const int tid = threadIdx.x;
    __shared__ __align__(16) float Xs[64][33];
    __shared__ __align__(16) float Ws[32][64];
    float acc[4][4];
    #pragma unroll
    for (int r = 0; r < 4; r++)
        #pragma unroll
        for (int c = 0; c < 4; c++) acc[r][c] = 0.f;

    const int fr = tid >> 4, cg = tid & 15;
    const float* Wh = W + (size_t)head * D * HID;

    for (int d0 = 0; d0 < D; d0 += 32) {
        {
            int j = tid & 31, n0 = (tid >> 5) * 8;
            #pragma unroll
            for (int i = 0; i < 8; i++)
                Xs[n0 + i][j] = X[(size_t)(r0 + n0 + i) * D + d0 + j];
        }
        {
            int o = tid & 63, j0 = (tid >> 6) * 8;
            #pragma unroll
            for (int i = 0; i < 8; i++)
                Ws[j0 + i][o] = Wh[(size_t)(d0 + j0 + i) * HID + o];
        }
        __syncthreads();
        #pragma unroll
        for (int k = 0; k < 32; k++) {
            float4 wv = *(const float4*)&Ws[k][cg * 4];
            float x0 = Xs[fr * 4 + 0][k];
            float x1 = Xs[fr * 4 + 1][k];
            float x2 = Xs[fr * 4 + 2][k];
            float x3 = Xs[fr * 4 + 3][k];
            acc[0][0] += x0 * wv.x; acc[0][1] += x0 * wv.y; acc[0][2] += x0 * wv.z; acc[0][3] += x0 * wv.w;
            acc[1][0] += x1 * wv.x; acc[1][1] += x1 * wv.y; acc[1][2] += x1 * wv.z; acc[1][3] += x1 * wv.w;
            acc[2][0] += x2 * wv.x; acc[2][1] += x2 * wv.y; acc[2][2] += x2 * wv.z; acc[2][3] += x2 * wv.w;
            acc[3][0] += x3 * wv.x; acc[3][1] += x3 * wv.y; acc[3][2] += x3 * wv.z; acc[3][3] += x3 * wv.w;
        }
        __syncthreads();
    }
    float* hp = g_h + ((size_t)head * NROWS + r0) * HID;
    #pragma unroll
    for (int r = 0; r < 4; r++) {
        *(float4*)&hp[(size_t)(fr * 4 + r) * HID + cg * 4] =
            make_float4(acc[r][0], acc[r][1], acc[r][2], acc[r][3]);
    }
}

// ---------------- 3. e_l / e_r per (head, node) ----------------
__global__ void compute_e_kernel(const float* __restrict__ a, int H) {
    int gw = (blockIdx.x * blockDim.x + threadIdx.x) >> 5;
    int lane = threadIdx.x & 31;
    if (gw >= H * NROWS) return;
    int head = gw >> 12;
    int n = gw & (NROWS - 1);
    const float* hp = g_h + ((size_t)head * NROWS + n) * HID;
    const float* ah = a + head * 2 * HID;
    float sl = 0.f, sr = 0.f;
    #pragma unroll
    for (int i = lane; i < HID; i += 32) {
        float hv = hp[i];
        sl += hv * ah[i];
        sr += hv * ah[HID + i];
    }
    #pragma unroll
    for (int off = 16; off; off >>= 1) {
        sl += __shfl_xor_sync(0xffffffffu, sl, off);
        sr += __shfl_xor_sync(0xffffffffu, sr, off);
    }
    if (lane == 0) {
        g_el[head * NROWS + n] = sl;
        g_er[head * NROWS + n] = sr;
    }
}

// ---------------- 4. per-head max of e_r ----------------
__global__ void emax_kernel() {
    int head = blockIdx.x;
    __shared__ float red[256];
    float m = -1e30f;
    for (int i = threadIdx.x; i < NROWS; i += 256)
        m = fmaxf(m, g_er[head * NROWS + i]);
    red[threadIdx.x] = m;
    __syncthreads();
    for (int s = 128; s; s >>= 1) {
        if (threadIdx.x < s) red[threadIdx.x] = fmaxf(red[threadIdx.x], red[threadIdx.x + s]);
        __syncthreads();
    }
    if (threadIdx.x == 0) g_emax[head] = red[0];
}

// ---------------- 5. fused masked-softmax attention (single pass, fixed shift) ----------------
__global__ __launch_bounds__(64) void attn_kernel(float* __restrict__ extOut,
                                                  int ostride, int doElu, int toBuf) {
    const int head = blockIdx.y;
    const int r0 = blockIdx.x * BR;
    const int tid = threadIdx.x;

    __shared__ __align__(16) float hs[BM][64];
    __shared__ __align__(16) float ps[BM][BR];
    __shared__ __align__(16) float ers[NROWS];
    __shared__ float dsum[BR];

    // stage all e_r for this head (16KB, coalesced)
    {
        const float4* er4 = (const float4*)(g_er + head * NROWS);
        float4* d4 = (float4*)ers;
        #pragma unroll
        for (int i = tid; i < NROWS / 4; i += 64) d4[i] = er4[i];
    }

    const float el = g_el[head * NROWS + r0 + tid];
    const float emax = g_emax[head];
    float M = el + emax;
    M = fmaxf(M, ALPHA * M);   // lrelu of the (>= true) max: safe shift, all exponents <= 0
    float dacc = 0.f;

    const int fr = tid >> 3;   // output rows fr*8 .. fr*8+7
    const int cg = tid & 7;    // output cols cg*8 .. cg*8+7
    unsigned long long acc[8][4];
    #pragma unroll
    for (int r = 0; r < 8; r++)
        #pragma unroll
        for (int c = 0; c < 4; c++) acc[r][c] = 0ULL;

    const float* hb = g_h + (size_t)head * NROWS * HID;
    const unsigned int* aw = g_adjbits + (size_t)(r0 + tid) * NW;

    __syncthreads();  // ers ready

    for (int m0 = 0; m0 < NROWS; m0 += BM) {
        // stage h tile [BM][64]
        #pragma unroll
        for (int i = 0; i < 8; i++) {
            int e = tid + i * 64;               // 512 float4s
            int row = e >> 4, c4 = (e & 15) << 2;
            *(float4*)&hs[row][c4] = *(const float4*)&hb[(size_t)(m0 + row) * HID + c4];
        }
        // generate p row for my node (thread tid owns row r0+tid)
        unsigned int word = aw[m0 >> 5];
        #pragma unroll
        for (int m = 0; m < BM; m++) {
            float s = el + ers[m0 + m];
            s = fmaxf(s, ALPHA * s);            // leaky relu
            float p = 0.f;
            if ((word >> m) & 1u) p = __expf(s - M);
            dacc += p;
            ps[m][tid] = p;
        }
        __syncthreads();
        // P @ h accumulation: 8x8 per-thread tile, packed f32x2 FMAs
        #pragma unroll
        for (int k = 0; k < BM; k++) {
            float4 pA = *(const float4*)&ps[k][fr * 8];
            float4 pB = *(const float4*)&ps[k][fr * 8 + 4];
            ulonglong2 hA = *(const ulonglong2*)&hs[k][cg * 8];
            ulonglong2 hB = *(const ulonglong2*)&hs[k][cg * 8 + 4];
            unsigned long long pp;
            pp = pack2(pA.x);
            fma2(acc[0][0], pp, hA.x); fma2(acc[0][1], pp, hA.y);
            fma2(acc[0][2], pp, hB.x); fma2(acc[0][3], pp, hB.y);
            pp = pack2(pA.y);
            fma2(acc[1][0], pp, hA.x); fma2(acc[1][1], pp, hA.y);
            fma2(acc[1][2], pp, hB.x); fma2(acc[1][3], pp, hB.y);
            pp = pack2(pA.z);
            fma2(acc[2][0], pp, hA.x); fma2(acc[2][1], pp, hA.y);
            fma2(acc[2][2], pp, hB.x); fma2(acc[2][3], pp, hB.y);
            pp = pack2(pA.w);
            fma2(acc[3][0], pp, hA.x); fma2(acc[3][1], pp, hA.y);
            fma2(acc[3][2], pp, hB.x); fma2(acc[3][3], pp, hB.y);
            pp = pack2(pB.x);
            fma2(acc[4][0], pp, hA.x); fma2(acc[4][1], pp, hA.y);
            fma2(acc[4][2], pp, hB.x); fma2(acc[4][3], pp, hB.y);
            pp = pack2(pB.y);
            fma2(acc[5][0], pp, hA.x); fma2(acc[5][1], pp, hA.y);
            fma2(acc[5][2], pp, hB.x); fma2(acc[5][3], pp, hB.y);
            pp = pack2(pB.z);
            fma2(acc[6][0], pp, hA.x); fma2(acc[6][1], pp, hA.y);
            fma2(acc[6][2], pp, hB.x); fma2(acc[6][3], pp, hB.y);
            pp = pack2(pB.w);
            fma2(acc[7][0], pp, hA.x); fma2(acc[7][1], pp, hA.y);
            fma2(acc[7][2], pp, hB.x); fma2(acc[7][3], pp, hB.y);
        }
        __syncthreads();
    }

    dsum[tid] = dacc;
    __syncthreads();

    float* obase = toBuf ? g_buf : extOut;
    #pragma unroll
    for (int r = 0; r < 8; r++) {
        int row = fr * 8 + r;
        float inv = 1.0f / dsum[row];
        float2 v0 = unpack2(acc[r][0]);
        float2 v1 = unpack2(acc[r][1]);
        float2 v2 = unpack2(acc[r][2]);
        float2 v3 = unpack2(acc[r][3]);
        float v[8] = {v0.x, v0.y, v1.x, v1.y, v2.x, v2.y, v3.x, v3.y};
        #pragma unroll
        for (int i = 0; i < 8; i++) {
            float t = v[i] * inv;
            if (doElu) t = (t > 0.f) ? t : expm1f(t);
            v[i] = t;
        }
        float* op = obase + (size_t)(r0 + row) * ostride + head * HID + cg * 8;
        *(float4*)op = make_float4(v[0], v[1], v[2], v[3]);
        *(float4*)(op + 4) = make_float4(v[4], v[5], v[6], v[7]);
    }
}

// ---------------- launch ----------------
extern "C" void kernel_launch(void* const* d_in, const int* in_sizes, int n_in,
                              void* d_out, int out_size) {
    const float* x  = (const float*)d_in[0];
    const int*   adj = (const int*)d_in[1];
    const float* W0 = (const float*)d_in[2];
    const float* a0 = (const float*)d_in[3];
    const float* W1 = (const float*)d_in[4];
    const float* a1 = (const float*)d_in[5];
    const float* W2 = (const float*)d_in[6];
    const float* a2 = (const float*)d_in[7];
    float* out = (float*)d_out;

    pack_adj_kernel<<<NROWS, 128>>>(adj);

    // layer 0: D=128, H=4, input = x, output -> g_buf (ELU)
    gemm_kernel<<<dim3(64, 4), 256>>>(x, W0, 128, 0);
    compute_e_kernel<<<4 * 512, 256>>>(a0, 4);
    emax_kernel<<<4, 256>>>();
    attn_kernel<<<dim3(64, 4), 64>>>(nullptr, 256, 1, 1);

    // layer 1: D=256, H=4, input = g_buf, output -> g_buf (ELU)
    gemm_kernel<<<dim3(64, 4), 256>>>(nullptr, W1, 256, 1);
    compute_e_kernel<<<4 * 512, 256>>>(a1, 4);
    emax_kernel<<<4, 256>>>();
    attn_kernel<<<dim3(64, 4), 64>>>(nullptr, 256, 1, 1);

    // layer 2: D=256, H=1, input = g_buf, output -> d_out (no ELU)
    gemm_kernel<<<dim3(64, 1), 256>>>(nullptr, W2, 256, 1);
    compute_e_kernel<<<512, 256>>>(a2, 1);
    emax_kernel<<<1, 256>>>();
    attn_kernel<<<dim3(64, 1), 64>>>(out, 64, 0, 0);
}

// round 2
// speedup vs baseline: 1.5906x; 1.5906x over previous
#include <cuda_runtime.h>
#include <math.h>

#define NROWS 4096
#define NW 128          // adjacency bitmask words per row (4096/32)
#define HID 64
#define ALPHA 0.2f
#define BR 64           // attention rows per block
#define BM 32           // attention m-chunk

// ---------------- device scratch ----------------
__device__ unsigned int g_adjbits[NROWS * NW];       // 2 MB packed adjacency
__device__ float g_h[4 * NROWS * HID];               // per-layer head features (4 MB)
__device__ float g_el[4 * NROWS];
__device__ float g_er[4 * NROWS];
__device__ unsigned int g_emax_u[4];                 // ordered-uint encoded per-head max(e_r)
__device__ float g_buf[NROWS * 256];                 // inter-layer activations (4 MB)
__device__ float g_pnum[64 * 4 * BR * HID];          // layer-2 partial numerators
__device__ float g_pden[64 * 4 * BR];                // layer-2 partial denominators

// ---------------- helpers ----------------
__device__ __forceinline__ unsigned long long pack2(float x) {
    unsigned long long r;
    asm("mov.b64 %0, {%1, %1};" : "=l"(r) : "f"(x));
    return r;
}
__device__ __forceinline__ void fma2(unsigned long long& d, unsigned long long a, unsigned long long b) {
    asm("fma.rn.f32x2 %0, %1, %2, %0;" : "+l"(d) : "l"(a), "l"(b));
}
__device__ __forceinline__ float2 unpack2(unsigned long long v) {
    float2 f;
    asm("mov.b64 {%0, %1}, %2;" : "=f"(f.x), "=f"(f.y) : "l"(v));
    return f;
}
__device__ __forceinline__ unsigned f2ord(float f) {
    unsigned u = __float_as_uint(f);
    return (u & 0x80000000u) ? ~u : (u | 0x80000000u);
}
__device__ __forceinline__ float ord2f(unsigned u) {
    return (u & 0x80000000u) ? __uint_as_float(u ^ 0x80000000u) : __uint_as_float(~u);
}

// ---------------- 1. pack adjacency into bitmask ----------------
__global__ void pack_adj_kernel(const int* __restrict__ adj) {
    int n = blockIdx.x;
    int warp = threadIdx.x >> 5, lane = threadIdx.x & 31;
    const int* row = adj + (size_t)n * NROWS;
    #pragma unroll 4
    for (int w = warp * 32; w < warp * 32 + 32; w++) {
        int v = row[w * 32 + lane];
        unsigned int bits = __ballot_sync(0xffffffffu, v > 0);
        if (lane == 0) g_adjbits[n * NW + w] = bits;
    }
}

// ---------------- 2. feature GEMM: g_h[head][n][o] = X @ W[head] ----------------
__global__ __launch_bounds__(256) void gemm_kernel(const float* __restrict__ Xext,
                                                   const float* __restrict__ W,
                                                   int D, int useBuf) {
    // deterministic reset of the per-layer emax accumulators (runs before compute_e)
    if (blockIdx.x == 0 && blockIdx.y == 0 && threadIdx.x < 4) g_emax_u[threadIdx.x] = 0u;

    const float* __restrict__ X = useBuf ? (const float*)g_buf : Xext;
    const int head = blockIdx.y;
    const int r0 = blockIdx.x * 64;
    const int tid = threadIdx.x;
    __shared__ __align__(16) float Xs[64][33];
    __shared__ __align__(16) float Ws[32][64];
    float acc[4][4];
    #pragma unroll
    for (int r = 0; r < 4; r++)
        #pragma unroll
        for (int c = 0; c < 4; c++) acc[r][c] = 0.f;

    const int fr = tid >> 4, cg = tid & 15;
    const float* Wh = W + (size_t)head * D * HID;

    for (int d0 = 0; d0 < D; d0 += 32) {
        {
            int j = tid & 31, n0 = (tid >> 5) * 8;
            #pragma unroll
            for (int i = 0; i < 8; i++)
                Xs[n0 + i][j] = X[(size_t)(r0 + n0 + i) * D + d0 + j];
        }
        {
            int o = tid & 63, j0 = (tid >> 6) * 8;
            #pragma unroll
            for (int i = 0; i < 8; i++)
                Ws[j0 + i][o] = Wh[(size_t)(d0 + j0 + i) * HID + o];
        }
        __syncthreads();
        #pragma unroll
        for (int k = 0; k < 32; k++) {
            float4 wv = *(const float4*)&Ws[k][cg * 4];
            float x0 = Xs[fr * 4 + 0][k];
            float x1 = Xs[fr * 4 + 1][k];
            float x2 = Xs[fr * 4 + 2][k];
            float x3 = Xs[fr * 4 + 3][k];
            acc[0][0] += x0 * wv.x; acc[0][1] += x0 * wv.y; acc[0][2] += x0 * wv.z; acc[0][3] += x0 * wv.w;
            acc[1][0] += x1 * wv.x; acc[1][1] += x1 * wv.y; acc[1][2] += x1 * wv.z; acc[1][3] += x1 * wv.w;
            acc[2][0] += x2 * wv.x; acc[2][1] += x2 * wv.y; acc[2][2] += x2 * wv.z; acc[2][3] += x2 * wv.w;
            acc[3][0] += x3 * wv.x; acc[3][1] += x3 * wv.y; acc[3][2] += x3 * wv.z; acc[3][3] += x3 * wv.w;
        }
        __syncthreads();
    }
    float* hp = g_h + ((size_t)head * NROWS + r0) * HID;
    #pragma unroll
    for (int r = 0; r < 4; r++) {
        *(float4*)&hp[(size_t)(fr * 4 + r) * HID + cg * 4] =
            make_float4(acc[r][0], acc[r][1], acc[r][2], acc[r][3]);
    }
}

// ---------------- 3. e_l / e_r per (head, node), fused per-head max(e_r) ----------------
__global__ void compute_e_kernel(const float* __restrict__ a, int H) {
    int gw = (blockIdx.x * blockDim.x + threadIdx.x) >> 5;
    int lane = threadIdx.x & 31;
    int head = gw >> 12;
    int n = gw & (NROWS - 1);
    __shared__ float wmax[8];
    const float* hp = g_h + ((size_t)head * NROWS + n) * HID;
    const float* ah = a + head * 2 * HID;
    float sl = 0.f, sr = 0.f;
    #pragma unroll
    for (int i = lane; i < HID; i += 32) {
        float hv = hp[i];
        sl += hv * ah[i];
        sr += hv * ah[HID + i];
    }
    #pragma unroll
    for (int off = 16; off; off >>= 1) {
        sl += __shfl_xor_sync(0xffffffffu, sl, off);
        sr += __shfl_xor_sync(0xffffffffu, sr, off);
    }
    if (lane == 0) {
        g_el[head * NROWS + n] = sl;
        g_er[head * NROWS + n] = sr;
        wmax[threadIdx.x >> 5] = sr;
    }
    __syncthreads();
    if (threadIdx.x == 0) {
        float m = wmax[0];
        #pragma unroll
        for (int i = 1; i < 8; i++) m = fmaxf(m, wmax[i]);
        atomicMax(&g_emax_u[head], f2ord(m));
    }
}

// ---------------- 4. fused masked-softmax attention ----------------
// 256 threads, 64x64 output tile, 4x4 per thread, packed-f32x2 P staged in smem.
__global__ __launch_bounds__(256) void attn_kernel(float* __restrict__ extOut,
                                                   int ostride, int doElu,
                                                   int toBuf, int partial) {
    const int head = blockIdx.y;
    const int r0 = blockIdx.x * BR;
    const int z = blockIdx.z;
    const int msplit = gridDim.z;
    const int mlen = NROWS / msplit;
    const int mstart = z * mlen;
    const int tid = threadIdx.x;

    __shared__ __align__(16) float hs[BM][HID];                 // 8 KB
    __shared__ __align__(16) unsigned long long ps2[BM][BR];    // 16 KB (pre-packed pairs)
    __shared__ __align__(16) float ers[NROWS];                  // 16 KB
    __shared__ float dsum4[4][BR];
    __shared__ float dsum[BR];

    // stage e_r slice (coalesced)
    {
        const float4* er4 = (const float4*)(g_er + head * NROWS + mstart);
        float4* d4 = (float4*)ers;
        for (int i = tid; i < mlen / 4; i += 256) d4[i] = er4[i];
    }

    const int row = tid & 63;      // score-gen: this thread's output row
    const int sub = tid >> 6;      // score-gen: m sub-range (8 per chunk)
    const float el = g_el[head * NROWS + r0 + row];
    const float emax = ord2f(g_emax_u[head]);
    float M = el + emax;
    M = fmaxf(M, ALPHA * M);       // lrelu of an upper bound: all exponents <= 0
    float dacc = 0.f;

    const int fr = tid >> 4;       // 16 row-groups x 4 rows
    const int cg = tid & 15;       // 16 col-groups x 4 cols
    unsigned long long acc[4][2];
    #pragma unroll
    for (int r = 0; r < 4; r++) { acc[r][0] = 0ULL; acc[r][1] = 0ULL; }

    const float* hb = g_h + (size_t)head * NROWS * HID;
    const unsigned int* aw = g_adjbits + (size_t)(r0 + row) * NW;

    __syncthreads();  // ers ready

    for (int m0 = mstart; m0 < mstart + mlen; m0 += BM) {
        // stage h tile [BM][64] (512 float4, 2 per thread)
        #pragma unroll
        for (int i = 0; i < 2; i++) {
            int e = tid + i * 256;
            int rr = e >> 4, c4 = (e & 15) << 2;
            *(float4*)&hs[rr][c4] = *(const float4*)&hb[(size_t)(m0 + rr) * HID + c4];
        }
        // generate 8 p-values for my row, pre-packed as f32x2 pairs
        unsigned int word = aw[m0 >> 5];
        const int mb = sub * 8;
        #pragma unroll
        for (int j = 0; j < 8; j++) {
            float s = el + ers[m0 - mstart + mb + j];
            s = fmaxf(s, ALPHA * s);                 // leaky relu
            float p = 0.f;
            if ((word >> (mb + j)) & 1u) p = __expf(s - M);
            dacc += p;
            ps2[mb + j][row] = pack2(p);
        }
        __syncthreads();
        // P @ h: 3 LDS.128 + 8 fma2 per k
        #pragma unroll
        for (int k = 0; k < BM; k++) {
            ulonglong2 pA = *(const ulonglong2*)&ps2[k][fr * 4];
            ulonglong2 pB = *(const ulonglong2*)&ps2[k][fr * 4 + 2];
            ulonglong2 hv = *(const ulonglong2*)&hs[k][cg * 4];
            fma2(acc[0][0], pA.x, hv.x); fma2(acc[0][1], pA.x, hv.y);
            fma2(acc[1][0], pA.y, hv.x); fma2(acc[1][1], pA.y, hv.y);
            fma2(acc[2][0], pB.x, hv.x); fma2(acc[2][1], pB.x, hv.y);
            fma2(acc[3][0], pB.y, hv.x); fma2(acc[3][1], pB.y, hv.y);
        }
        __syncthreads();
    }

    dsum4[sub][row] = dacc;
    __syncthreads();
    if (tid < BR) dsum[tid] = dsum4[0][tid] + dsum4[1][tid] + dsum4[2][tid] + dsum4[3][tid];
    __syncthreads();

    if (!partial) {
        float* obase = toBuf ? g_buf : extOut;
        #pragma unroll
        for (int r = 0; r < 4; r++) {
            int ri = fr * 4 + r;
            float inv = 1.0f / dsum[ri];
            float2 v0 = unpack2(acc[r][0]);
            float2 v1 = unpack2(acc[r][1]);
            float v[4] = {v0.x, v0.y, v1.x, v1.y};
            #pragma unroll
            for (int i = 0; i < 4; i++) {
                float t = v[i] * inv;
                if (doElu) t = (t > 0.f) ? t : expm1f(t);
                v[i] = t;
            }
            *(float4*)(obase + (size_t)(r0 + ri) * ostride + head * HID + cg * 4) =
                make_float4(v[0], v[1], v[2], v[3]);
        }
    } else {
        float* np = g_pnum + ((size_t)blockIdx.x * msplit + z) * (BR * HID);
        #pragma unroll
        for (int r = 0; r < 4; r++) {
            int ri = fr * 4 + r;
            float2 v0 = unpack2(acc[r][0]);
            float2 v1 = unpack2(acc[r][1]);
            *(float4*)(np + ri * HID + cg * 4) = make_float4(v0.x, v0.y, v1.x, v1.y);
        }
        if (tid < BR) g_pden[((size_t)blockIdx.x * msplit + z) * BR + tid] = dsum[tid];
    }
}

// ---------------- 5. combine layer-2 partials ----------------
__global__ void combine_kernel(float* __restrict__ out) {
    int b = blockIdx.x;
    for (int idx = threadIdx.x; idx < BR * HID; idx += 256) {
        int row = idx >> 6;
        float num = 0.f, den = 0.f;
        #pragma unroll
        for (int zz = 0; zz < 4; zz++) {
            num += g_pnum[((size_t)b * 4 + zz) * (BR * HID) + idx];
            den += g_pden[((size_t)b * 4 + zz) * BR + row];
        }
        out[(size_t)(b * BR + row) * HID + (idx & 63)] = num / den;
    }
}

// ---------------- launch ----------------
extern "C" void kernel_launch(void* const* d_in, const int* in_sizes, int n_in,
                              void* d_out, int out_size) {
    const float* x   = (const float*)d_in[0];
    const int*   adj = (const int*)d_in[1];
    const float* W0  = (const float*)d_in[2];
    const float* a0  = (const float*)d_in[3];
    const float* W1  = (const float*)d_in[4];
    const float* a1  = (const float*)d_in[5];
    const float* W2  = (const float*)d_in[6];
    const float* a2  = (const float*)d_in[7];
    float* out = (float*)d_out;

    pack_adj_kernel<<<NROWS, 128>>>(adj);

    // layer 0: D=128, H=4, input = x, output -> g_buf (ELU)
    gemm_kernel<<<dim3(64, 4), 256>>>(x, W0, 128, 0);
    compute_e_kernel<<<4 * 512, 256>>>(a0, 4);
    attn_kernel<<<dim3(64, 4, 1), 256>>>(nullptr, 256, 1, 1, 0);

    // layer 1: D=256, H=4, input = g_buf, output -> g_buf (ELU)
    gemm_kernel<<<dim3(64, 4), 256>>>(nullptr, W1, 256, 1);
    compute_e_kernel<<<4 * 512, 256>>>(a1, 4);
    attn_kernel<<<dim3(64, 4, 1), 256>>>(nullptr, 256, 1, 1, 0);

    // layer 2: D=256, H=1, input = g_buf, output -> d_out (no ELU), m-split=4
    gemm_kernel<<<dim3(64, 1), 256>>>(nullptr, W2, 256, 1);
    compute_e_kernel<<<512, 256>>>(a2, 1);
    attn_kernel<<<dim3(64, 1, 4), 256>>>(nullptr, 0, 0, 0, 1);
    combine_kernel<<<64, 256>>>(out);
}